// round 2
// baseline (speedup 1.0000x reference)
#include <cuda_runtime.h>

#define N_SAMP 8192
#define EMB    128
#define NBINS  10
#define LBINS  11        // NBINS + 1 bin centers
#define HPITCH 24        // per-row hist: [0..10]=pos, [12..22]=neg
#define BM     128       // rows per block
#define PITCH  132       // smem row pitch (floats), 132%32=4 and 4-aligned for float4
#define CT     4         // column sub-tiles per block (block covers 512 cols)

// ---- device scratch (no allocations allowed) ----
__device__ float g_hist[N_SAMP * HPITCH];   // per-row soft histograms
__device__ int   g_cls[8192];               // class counts (labels < 100, oversized for safety)
__device__ float g_ap_sum;
__device__ float g_nvalid;

__global__ void zero_kernel() {
    int i = blockIdx.x * blockDim.x + threadIdx.x;
    int stride = gridDim.x * blockDim.x;
    for (int idx = i; idx < N_SAMP * HPITCH; idx += stride) g_hist[idx] = 0.0f;
    for (int idx = i; idx < 8192; idx += stride) g_cls[idx] = 0;
    if (i == 0) { g_ap_sum = 0.0f; g_nvalid = 0.0f; }
}

__global__ void count_kernel(const int* __restrict__ labels) {
    int i = blockIdx.x * blockDim.x + threadIdx.x;
    if (i < N_SAMP) {
        int l = labels[i];
        if (l >= 0 && l < 8192) atomicAdd(&g_cls[l], 1);
    }
}

extern __shared__ float smem_dyn[];

// Fused GEMM (X X^T) + soft-binning histogram.
// Grid: (16 col-groups of 512, 64 row-groups of 128). 256 threads, 8x8 microtile,
// strided mapping (row = ty + i*16, col = tx + j*16) for conflict-free LDS.
__global__ __launch_bounds__(256, 1)
void hist_kernel(const float* __restrict__ X, const int* __restrict__ labels) {
    float* sA    = smem_dyn;                 // [BM][PITCH]
    float* sB    = sA + BM * PITCH;          // [BM][PITCH]
    float* sHist = sB + BM * PITCH;          // [BM][HPITCH]
    int*   sLabA = (int*)(sHist + BM * HPITCH);
    int*   sLabB = sLabA + BM;

    const int tid = threadIdx.x;
    const int tx  = tid & 15;
    const int ty  = tid >> 4;
    const int rowBase  = blockIdx.y * BM;
    const int colGroup = blockIdx.x * (BM * CT);

    // Load A tile (128 rows x 128 k) via float4, row-major smem
    for (int idx = tid; idx < BM * 32; idx += 256) {
        int row = idx >> 5;
        int kv  = idx & 31;
        float4 v = ((const float4*)X)[(size_t)(rowBase + row) * 32 + kv];
        *(float4*)&sA[row * PITCH + kv * 4] = v;
    }
    if (tid < BM) sLabA[tid] = labels[rowBase + tid];
    for (int idx = tid; idx < BM * HPITCH; idx += 256) sHist[idx] = 0.0f;
    __syncthreads();

    for (int ct = 0; ct < CT; ct++) {
        const int colBase = colGroup + ct * BM;

        for (int idx = tid; idx < BM * 32; idx += 256) {
            int row = idx >> 5;
            int kv  = idx & 31;
            float4 v = ((const float4*)X)[(size_t)(colBase + row) * 32 + kv];
            *(float4*)&sB[row * PITCH + kv * 4] = v;
        }
        if (tid < BM) sLabB[tid] = labels[colBase + tid];
        __syncthreads();

        float acc[8][8];
        #pragma unroll
        for (int i = 0; i < 8; i++)
            #pragma unroll
            for (int j = 0; j < 8; j++) acc[i][j] = 0.0f;

        #pragma unroll 4
        for (int k = 0; k < EMB; k++) {
            float a[8], b[8];
            #pragma unroll
            for (int i = 0; i < 8; i++) a[i] = sA[(ty + i * 16) * PITCH + k];
            #pragma unroll
            for (int j = 0; j < 8; j++) b[j] = sB[(tx + j * 16) * PITCH + k];
            #pragma unroll
            for (int i = 0; i < 8; i++)
                #pragma unroll
                for (int j = 0; j < 8; j++)
                    acc[i][j] = fmaf(a[i], b[j], acc[i][j]);
        }

        // Epilogue: soft-bin each dot product into per-row pos/neg histograms.
        #pragma unroll
        for (int i = 0; i < 8; i++) {
            const int rl   = ty + i * 16;
            const int grow = rowBase + rl;
            const int labA = sLabA[rl];
            #pragma unroll
            for (int j = 0; j < 8; j++) {
                const int cl   = tx + j * 16;
                const int gcol = colBase + cl;
                if (grow == gcol) continue;      // exclude diagonal
                float d = 2.0f - 2.0f * acc[i][j];
                d = fminf(fmaxf(d, 0.0f), 4.0f);
                float t = d * 2.5f;              // d / Delta, Delta = 0.4
                int l0 = (int)t;
                l0 = min(l0, NBINS - 1);
                float frac = t - (float)l0;
                int base = rl * HPITCH + ((labA == sLabB[cl]) ? 0 : 12);
                atomicAdd(&sHist[base + l0],     1.0f - frac);
                atomicAdd(&sHist[base + l0 + 1], frac);
            }
        }
        __syncthreads();
    }

    // Flush block-local histograms to global
    for (int idx = tid; idx < BM * HPITCH; idx += 256) {
        float v = sHist[idx];
        if (v != 0.0f) {
            int row = idx / HPITCH;
            int c   = idx - row * HPITCH;
            atomicAdd(&g_hist[(rowBase + row) * HPITCH + c], v);
        }
    }
}

__global__ void finalize_kernel(const int* __restrict__ labels) {
    int i = blockIdx.x * blockDim.x + threadIdx.x;
    float val = 0.0f, valid = 0.0f;
    if (i < N_SAMP) {
        const float* h = &g_hist[i * HPITCH];
        float Hp = 0.0f, H = 0.0f, ap = 0.0f;
        #pragma unroll
        for (int l = 0; l < LBINS; l++) {
            float hp = h[l];
            float hn = h[12 + l];
            Hp += hp;
            H  += hp + hn;
            if (H > 0.0f) ap += hp * Hp / H;
        }
        int np = g_cls[labels[i]] - 1;   // exact N_pos
        if (np > 0) { val = ap / (float)np; valid = 1.0f; }
    }
    #pragma unroll
    for (int off = 16; off > 0; off >>= 1) {
        val   += __shfl_down_sync(0xffffffffu, val, off);
        valid += __shfl_down_sync(0xffffffffu, valid, off);
    }
    if ((threadIdx.x & 31) == 0) {
        atomicAdd(&g_ap_sum, val);
        atomicAdd(&g_nvalid, valid);
    }
}

__global__ void loss_kernel(float* out) {
    out[0] = 1.0f - g_ap_sum / g_nvalid;
}

extern "C" void kernel_launch(void* const* d_in, const int* in_sizes, int n_in,
                              void* d_out, int out_size) {
    const float* X      = (const float*)d_in[0];
    const int*   labels = (const int*)d_in[1];
    float*       out    = (float*)d_out;

    const size_t SMEM = (size_t)(2 * BM * PITCH + BM * HPITCH) * sizeof(float)
                        + (size_t)(2 * BM) * sizeof(int);
    cudaFuncSetAttribute(hist_kernel, cudaFuncAttributeMaxDynamicSharedMemorySize, (int)SMEM);

    zero_kernel<<<256, 256>>>();
    count_kernel<<<(N_SAMP + 255) / 256, 256>>>(labels);

    dim3 grid(N_SAMP / (BM * CT), N_SAMP / BM);   // (16, 64)
    hist_kernel<<<grid, 256, SMEM>>>(X, labels);

    finalize_kernel<<<(N_SAMP + 255) / 256, 256>>>(labels);
    loss_kernel<<<1, 1>>>(out);
}

// round 4
// speedup vs baseline: 1.9526x; 1.9526x over previous
#include <cuda_runtime.h>
#include <cstdint>

#define N_SAMP 8192
#define EMB    128
#define NBINS  10
#define LBINS  11
#define HPITCH 24        // global per-row hist: [0..10]=pos, [12..22]=neg
#define BM     128       // rows per block tile
#define PITCH  130       // smem row pitch in floats: bank stride 2 -> conflict-free LDS.64
#define CT     4         // column sub-tiles per block (block covers 512 cols)
#define SLICES 4         // atomic contention slices
#define HROW   (HPITCH * SLICES)   // 96 floats per row in smem hist

// ---- device scratch (no allocations allowed) ----
__device__ float g_hist[N_SAMP * HPITCH];
__device__ int   g_cls[8192];
__device__ float g_ap_sum;
__device__ float g_nvalid;

__global__ void zero_kernel() {
    int i = blockIdx.x * blockDim.x + threadIdx.x;
    int stride = gridDim.x * blockDim.x;
    for (int idx = i; idx < N_SAMP * HPITCH; idx += stride) g_hist[idx] = 0.0f;
    for (int idx = i; idx < 8192; idx += stride) g_cls[idx] = 0;
    if (i == 0) { g_ap_sum = 0.0f; g_nvalid = 0.0f; }
}

__global__ void count_kernel(const int* __restrict__ labels) {
    int i = blockIdx.x * blockDim.x + threadIdx.x;
    if (i < N_SAMP) {
        int l = labels[i];
        if (l >= 0 && l < 8192) atomicAdd(&g_cls[l], 1);
    }
}

extern __shared__ float smem_dyn[];

__device__ __forceinline__ unsigned long long ffma2(unsigned long long a,
                                                    unsigned long long b,
                                                    unsigned long long c) {
    unsigned long long d;
    asm("fma.rn.f32x2 %0, %1, %2, %3;" : "=l"(d) : "l"(a), "l"(b), "l"(c));
    return d;
}

// Fused GEMM (X X^T) + soft-binning histogram.
// 256 threads, 8x8 microtile, strided mapping (row = ty + i*16, col = tx + j*16).
// K dimension processed in packed f32x2 pairs (FFMA2), LDS.64 conflict-free.
__global__ __launch_bounds__(256, 1)
void hist_kernel(const float* __restrict__ X, const int* __restrict__ labels) {
    float* sA    = smem_dyn;                   // [BM][PITCH]
    float* sB    = sA + BM * PITCH;            // [BM][PITCH]
    float* sHist = sB + BM * PITCH;            // [BM][HROW]  (pos bins*4, neg bins*4)
    int*   sLabA = (int*)(sHist + BM * HROW);
    int*   sLabB = sLabA + BM;

    const int tid = threadIdx.x;
    const int tx  = tid & 15;
    const int ty  = tid >> 4;
    const int slice = tid & (SLICES - 1);
    const int rowBase  = blockIdx.y * BM;
    const int colGroup = blockIdx.x * (BM * CT);

    // Load A tile (128 rows x 128 k): float4 global -> two float2 smem stores
    for (int idx = tid; idx < BM * 32; idx += 256) {
        int row = idx >> 5;
        int kv  = idx & 31;
        float4 v = ((const float4*)X)[(size_t)(rowBase + row) * 32 + kv];
        float* dst = &sA[row * PITCH + kv * 4];
        *(float2*)(dst)     = make_float2(v.x, v.y);
        *(float2*)(dst + 2) = make_float2(v.z, v.w);
    }
    if (tid < BM) sLabA[tid] = labels[rowBase + tid];
    for (int idx = tid; idx < BM * HROW; idx += 256) sHist[idx] = 0.0f;
    __syncthreads();

    for (int ct = 0; ct < CT; ct++) {
        const int colBase = colGroup + ct * BM;

        for (int idx = tid; idx < BM * 32; idx += 256) {
            int row = idx >> 5;
            int kv  = idx & 31;
            float4 v = ((const float4*)X)[(size_t)(colBase + row) * 32 + kv];
            float* dst = &sB[row * PITCH + kv * 4];
            *(float2*)(dst)     = make_float2(v.x, v.y);
            *(float2*)(dst + 2) = make_float2(v.z, v.w);
        }
        if (tid < BM) sLabB[tid] = labels[colBase + tid];
        __syncthreads();

        unsigned long long acc[8][8];
        #pragma unroll
        for (int i = 0; i < 8; i++)
            #pragma unroll
            for (int j = 0; j < 8; j++) acc[i][j] = 0ULL;

        #pragma unroll 2
        for (int k2 = 0; k2 < EMB / 2; k2++) {
            const int k = k2 * 2;
            unsigned long long a2[8], b2[8];
            #pragma unroll
            for (int i = 0; i < 8; i++)
                a2[i] = *(const unsigned long long*)&sA[(ty + i * 16) * PITCH + k];
            #pragma unroll
            for (int j = 0; j < 8; j++)
                b2[j] = *(const unsigned long long*)&sB[(tx + j * 16) * PITCH + k];
            #pragma unroll
            for (int i = 0; i < 8; i++)
                #pragma unroll
                for (int j = 0; j < 8; j++)
                    acc[i][j] = ffma2(a2[i], b2[j], acc[i][j]);
        }

        // Epilogue: soft-bin each dot product into sliced per-row histograms.
        #pragma unroll
        for (int i = 0; i < 8; i++) {
            const int rl   = ty + i * 16;
            const int grow = rowBase + rl;
            const int labA = sLabA[rl];
            float* hrow = &sHist[rl * HROW];
            #pragma unroll
            for (int j = 0; j < 8; j++) {
                const int cl   = tx + j * 16;
                const int gcol = colBase + cl;
                if (grow == gcol) continue;      // exclude diagonal
                float2 p = *(float2*)&acc[i][j];
                float dot = p.x + p.y;
                float d = 2.0f - 2.0f * dot;
                d = fminf(fmaxf(d, 0.0f), 4.0f);
                float t = d * 2.5f;              // d / Delta, Delta = 0.4
                int l0 = (int)t;
                l0 = min(l0, NBINS - 1);
                float frac = t - (float)l0;
                // pos bins occupy [0,12), neg bins [12,24); 4 slices each
                int base = ((labA == sLabB[cl]) ? 0 : 12 * SLICES)
                           + l0 * SLICES + slice;
                atomicAdd(&hrow[base],          1.0f - frac);
                atomicAdd(&hrow[base + SLICES], frac);
            }
        }
        __syncthreads();
    }

    // Flush: reduce 4 slices, add once to global hist
    for (int idx = tid; idx < BM * HPITCH; idx += 256) {
        int row = idx / HPITCH;
        int c   = idx - row * HPITCH;
        const float* s = &sHist[row * HROW + c * SLICES];
        float v = s[0] + s[1] + s[2] + s[3];
        if (v != 0.0f)
            atomicAdd(&g_hist[(rowBase + row) * HPITCH + c], v);
    }
}

__global__ void finalize_kernel(const int* __restrict__ labels) {
    int i = blockIdx.x * blockDim.x + threadIdx.x;
    float val = 0.0f, valid = 0.0f;
    if (i < N_SAMP) {
        const float* h = &g_hist[i * HPITCH];
        float Hp = 0.0f, H = 0.0f, ap = 0.0f;
        #pragma unroll
        for (int l = 0; l < LBINS; l++) {
            float hp = h[l];
            float hn = h[12 + l];
            Hp += hp;
            H  += hp + hn;
            if (H > 0.0f) ap += hp * Hp / H;
        }
        int np = g_cls[labels[i]] - 1;
        if (np > 0) { val = ap / (float)np; valid = 1.0f; }
    }
    #pragma unroll
    for (int off = 16; off > 0; off >>= 1) {
        val   += __shfl_down_sync(0xffffffffu, val, off);
        valid += __shfl_down_sync(0xffffffffu, valid, off);
    }
    if ((threadIdx.x & 31) == 0) {
        atomicAdd(&g_ap_sum, val);
        atomicAdd(&g_nvalid, valid);
    }
}

__global__ void loss_kernel(float* out) {
    out[0] = 1.0f - g_ap_sum / g_nvalid;
}

extern "C" void kernel_launch(void* const* d_in, const int* in_sizes, int n_in,
                              void* d_out, int out_size) {
    const float* X      = (const float*)d_in[0];
    const int*   labels = (const int*)d_in[1];
    float*       out    = (float*)d_out;

    const size_t SMEM = (size_t)(2 * BM * PITCH + BM * HROW) * sizeof(float)
                        + (size_t)(2 * BM) * sizeof(int);
    cudaFuncSetAttribute(hist_kernel, cudaFuncAttributeMaxDynamicSharedMemorySize, (int)SMEM);

    zero_kernel<<<256, 256>>>();
    count_kernel<<<(N_SAMP + 255) / 256, 256>>>(labels);

    dim3 grid(N_SAMP / (BM * CT), N_SAMP / BM);   // (16, 64)
    hist_kernel<<<grid, 256, SMEM>>>(X, labels);

    finalize_kernel<<<(N_SAMP + 255) / 256, 256>>>(labels);
    loss_kernel<<<1, 1>>>(out);
}

// round 8
// speedup vs baseline: 9.6735x; 4.9542x over previous
#include <cuda_runtime.h>
#include <cuda_bf16.h>
#include <cstdint>

#define N_SAMP  8192
#define EMB     128
#define NBINS   10
#define LBINS   11
#define HP      16
#define THREADS 512
#define CG      2                    // col groups (grid.x)
#define TPC     (64 / CG)            // 32 col tiles of 128 per CTA
#define PB      272                  // smem tile row pitch in bytes (136 bf16)
#define TILE_SM (128 * PB)           // 34816 B per 128x128 bf16 tile

// ---------------- device scratch ----------------
__device__ __nv_bfloat16 g_Xb[N_SAMP * EMB];   // bf16 X, row-major (K-major)
__device__ float g_all[N_SAMP * HP];           // all-pairs soft hist
__device__ float g_pos[N_SAMP * HP];           // positive-pair soft hist
__device__ int   g_cls[8192];
__device__ float g_ap_sum;
__device__ float g_nvalid;

// ---------------- PTX helpers ----------------
static __device__ __forceinline__ uint32_t s2u(const void* p) {
    uint32_t a;
    asm("{ .reg .u64 t; cvta.to.shared.u64 t, %1; cvt.u32.u64 %0, t; }" : "=r"(a) : "l"(p));
    return a;
}
#define CP_ASYNC16(dst, src) \
    asm volatile("cp.async.cg.shared.global [%0], [%1], 16;" :: "r"(dst), "l"(src) : "memory")
#define CP_COMMIT() asm volatile("cp.async.commit_group;" ::: "memory")
#define CP_WAIT0()  asm volatile("cp.async.wait_group 0;" ::: "memory")

#define LDSM4(R, addr) \
    asm volatile("ldmatrix.sync.aligned.m8n8.x4.shared.b16 {%0,%1,%2,%3}, [%4];" \
        : "=r"((R)[0]), "=r"((R)[1]), "=r"((R)[2]), "=r"((R)[3]) : "r"(addr))

#define MMA16816(C, A, b0v, b1v) \
    asm volatile("mma.sync.aligned.m16n8k16.row.col.f32.bf16.bf16.f32 " \
        "{%0,%1,%2,%3},{%4,%5,%6,%7},{%8,%9},{%0,%1,%2,%3};" \
        : "+f"((C)[0]), "+f"((C)[1]), "+f"((C)[2]), "+f"((C)[3]) \
        : "r"((A)[0]), "r"((A)[1]), "r"((A)[2]), "r"((A)[3]), "r"(b0v), "r"(b1v))

// ---------------- small kernels ----------------
__global__ void zero_kernel() {
    int i = blockIdx.x * blockDim.x + threadIdx.x;
    int stride = gridDim.x * blockDim.x;
    for (int idx = i; idx < N_SAMP * HP; idx += stride) { g_all[idx] = 0.0f; g_pos[idx] = 0.0f; }
    for (int idx = i; idx < 8192; idx += stride) g_cls[idx] = 0;
    if (i == 0) { g_ap_sum = 0.0f; g_nvalid = 0.0f; }
}

__global__ void count_kernel(const int* __restrict__ labels) {
    int i = blockIdx.x * blockDim.x + threadIdx.x;
    if (i < N_SAMP) {
        int l = labels[i];
        if (l >= 0 && l < 8192) atomicAdd(&g_cls[l], 1);
    }
}

__global__ void prep_kernel(const float* __restrict__ X) {
    int i = blockIdx.x * blockDim.x + threadIdx.x;     // N_SAMP * 64
    if (i < N_SAMP * (EMB / 2)) {
        float2 v = ((const float2*)X)[i];
        ((__nv_bfloat162*)g_Xb)[i] = __float22bfloat162_rn(v);
    }
}

// ---------------- fused HMMA GEMM + soft-hist ----------------
// grid (CG, 64): blockIdx.y = 128-row block, blockIdx.x = group of TPC col tiles.
// 16 warps in a 4x4 (m x n) grid; warp tile 32x32; mma m16n8k16 bf16.
extern __shared__ char smem_raw[];

__global__ __launch_bounds__(THREADS, 1)
void hist_kernel(const int* __restrict__ labels) {
    const int tid  = threadIdx.x;
    const int lane = tid & 31;
    const int warp = tid >> 5;
    const int wm   = warp >> 2;          // 0..3: row quarter (32 rows)
    const int wn   = warp & 3;           // 0..3: col quarter (32 cols)
    const int rb   = blockIdx.y;
    const int cg   = blockIdx.x;

    const uint32_t uS = s2u(smem_raw);
    const uint32_t uA = uS;
    const uint32_t uBb[2] = { uS + TILE_SM, uS + 2 * TILE_SM };
    int* sLab = (int*)(smem_raw + 3 * TILE_SM);     // [2][128]

    // ---- load A tile + B tile 0 via cp.async ----
    {
        const char* gA = (const char*)(g_Xb + (size_t)rb * 128 * EMB);
        for (int i = tid; i < 2048; i += THREADS) {
            int row = i >> 4, c = i & 15;
            CP_ASYNC16(uA + row * PB + c * 16, gA + row * 256 + c * 16);
        }
        int tc = cg * TPC;
        const char* gB = (const char*)(g_Xb + (size_t)tc * 128 * EMB);
        for (int i = tid; i < 2048; i += THREADS) {
            int row = i >> 4, c = i & 15;
            CP_ASYNC16(uBb[0] + row * PB + c * 16, gB + row * 256 + c * 16);
        }
        if (tid < 128) sLab[tid] = labels[tc * 128 + tid];
    }
    CP_COMMIT();
    CP_WAIT0();
    __syncthreads();

    const int g  = lane >> 2;
    const int tq = lane & 3;

    int lrow[4], myLab[4];
    lrow[0] = wm * 32 + g;  lrow[1] = lrow[0] + 8;
    lrow[2] = lrow[0] + 16; lrow[3] = lrow[0] + 24;
    #pragma unroll
    for (int r = 0; r < 4; r++) myLab[r] = labels[rb * 128 + lrow[r]];

    int lcol[8];
    #pragma unroll
    for (int j = 0; j < 4; j++) {
        lcol[j * 2]     = wn * 32 + j * 8 + tq * 2;
        lcol[j * 2 + 1] = lcol[j * 2] + 1;
    }

    float h[4][7];
    #pragma unroll
    for (int r = 0; r < 4; r++)
        #pragma unroll
        for (int b = 0; b < 7; b++) h[r][b] = 0.0f;

    // ldmatrix lane address bases
    const uint32_t aBase = uA + (uint32_t)((wm * 32 + (lane & 15)) * PB + (lane >> 4) * 16);
    const uint32_t bRowOff = (uint32_t)((wn * 32 + (lane & 7) + ((lane >> 4) & 1) * 8) * PB
                                        + ((lane >> 3) & 1) * 16);

    for (int t = 0; t < TPC; t++) {
        const int buf = t & 1;

        // prefetch B[t+1]
        if (t + 1 < TPC) {
            int tc = cg * TPC + t + 1;
            const char* gB = (const char*)(g_Xb + (size_t)tc * 128 * EMB);
            uint32_t dB = uBb[buf ^ 1];
            for (int i = tid; i < 2048; i += THREADS) {
                int row = i >> 4, c = i & 15;
                CP_ASYNC16(dB + row * PB + c * 16, gB + row * 256 + c * 16);
            }
            CP_COMMIT();
            if (tid < 128) sLab[(buf ^ 1) * 128 + tid] = labels[tc * 128 + tid];
        }

        // ---- GEMM: 128x128 tile, warp computes 32x32 ----
        float acc[2][4][4];
        #pragma unroll
        for (int mi = 0; mi < 2; mi++)
            #pragma unroll
            for (int j = 0; j < 4; j++)
                #pragma unroll
                for (int e = 0; e < 4; e++) acc[mi][j][e] = 0.0f;

        const uint32_t uBt = uBb[buf] + bRowOff;
        #pragma unroll
        for (int kc = 0; kc < 8; kc++) {
            uint32_t A0[4], A1[4], B0[4], B1[4];
            LDSM4(A0, aBase + kc * 32);
            LDSM4(A1, aBase + 16 * PB + kc * 32);
            LDSM4(B0, uBt + kc * 32);             // n-tiles 0,1
            LDSM4(B1, uBt + 16 * PB + kc * 32);   // n-tiles 2,3
            MMA16816(acc[0][0], A0, B0[0], B0[1]);
            MMA16816(acc[0][1], A0, B0[2], B0[3]);
            MMA16816(acc[0][2], A0, B1[0], B1[1]);
            MMA16816(acc[0][3], A0, B1[2], B1[3]);
            MMA16816(acc[1][0], A1, B0[0], B0[1]);
            MMA16816(acc[1][1], A1, B0[2], B0[3]);
            MMA16816(acc[1][2], A1, B1[0], B1[1]);
            MMA16816(acc[1][3], A1, B1[2], B1[3]);
        }

        // ---- epilogue: soft-bin 32 dot products ----
        const int tileCol  = cg * TPC + t;
        const bool diagTile = (tileCol == rb);
        int clab[8];
        #pragma unroll
        for (int li = 0; li < 8; li++) clab[li] = sLab[buf * 128 + lcol[li]];

        #pragma unroll
        for (int mi = 0; mi < 2; mi++) {
            #pragma unroll
            for (int j = 0; j < 4; j++) {
                #pragma unroll
                for (int e = 0; e < 4; e++) {
                    const int ri = mi * 2 + (e >> 1);
                    const int li = j * 2 + (e & 1);
                    float tv = fmaf(acc[mi][j][e], -5.0f, 5.0f);   // 2.5 * dist2
                    bool isdiag = diagTile && (lcol[li] == lrow[ri]);
                    if (!isdiag) {
                        #pragma unroll
                        for (int b = 0; b < 7; b++)
                            h[ri][b] += fmaxf(1.0f - fabsf(tv - (float)(b + 2)), 0.0f);
                        if (clab[li] == myLab[ri]) {               // positive pair (~1%)
                            int grow = rb * 128 + lrow[ri];
                            float tp = fmaxf(tv, 0.0f);
                            int l0 = min((int)tp, 9);
                            float fr = tp - (float)l0;
                            atomicAdd(&g_pos[grow * HP + l0],     1.0f - fr);
                            atomicAdd(&g_pos[grow * HP + l0 + 1], fr);
                        }
                        if (tv < 3.0f) {                           // bins 0,1 (rare)
                            int grow = rb * 128 + lrow[ri];
                            float w0 = 1.0f - fabsf(tv);
                            float w1 = 1.0f - fabsf(tv - 1.0f);
                            if (w0 > 0.0f) atomicAdd(&g_all[grow * HP + 0], w0);
                            if (w1 > 0.0f) atomicAdd(&g_all[grow * HP + 1], w1);
                        }
                        if (tv > 7.0f) {                           // bins 9,10 (rare)
                            int grow = rb * 128 + lrow[ri];
                            float w9  = 1.0f - fabsf(tv - 9.0f);
                            float w10 = 1.0f - fabsf(tv - 10.0f);
                            if (w9  > 0.0f) atomicAdd(&g_all[grow * HP + 9],  w9);
                            if (w10 > 0.0f) atomicAdd(&g_all[grow * HP + 10], w10);
                        }
                    }
                }
            }
        }

        CP_WAIT0();
        __syncthreads();
    }

    // flush register hists (bins 2..8)
    #pragma unroll
    for (int ri = 0; ri < 4; ri++) {
        int grow = rb * 128 + lrow[ri];
        #pragma unroll
        for (int b = 0; b < 7; b++)
            atomicAdd(&g_all[grow * HP + 2 + b], h[ri][b]);
    }
}

// ---------------- finalize ----------------
__global__ void finalize_kernel(const int* __restrict__ labels) {
    int i = blockIdx.x * blockDim.x + threadIdx.x;
    float val = 0.0f, valid = 0.0f;
    if (i < N_SAMP) {
        const float* ha = &g_all[i * HP];
        const float* hp = &g_pos[i * HP];
        float Hp = 0.0f, H = 0.0f, ap = 0.0f;
        #pragma unroll
        for (int l = 0; l < LBINS; l++) {
            float p = hp[l];
            float a = ha[l];
            Hp += p;
            H  += a;
            if (H > 0.0f) ap += p * Hp / H;
        }
        int np = g_cls[labels[i]] - 1;
        if (np > 0) { val = ap / (float)np; valid = 1.0f; }
    }
    #pragma unroll
    for (int off = 16; off > 0; off >>= 1) {
        val   += __shfl_down_sync(0xffffffffu, val, off);
        valid += __shfl_down_sync(0xffffffffu, valid, off);
    }
    if ((threadIdx.x & 31) == 0) {
        atomicAdd(&g_ap_sum, val);
        atomicAdd(&g_nvalid, valid);
    }
}

__global__ void loss_kernel(float* out) {
    out[0] = 1.0f - g_ap_sum / g_nvalid;
}

// ---------------- launch ----------------
extern "C" void kernel_launch(void* const* d_in, const int* in_sizes, int n_in,
                              void* d_out, int out_size) {
    const float* X      = (const float*)d_in[0];
    const int*   labels = (const int*)d_in[1];
    float*       out    = (float*)d_out;

    const int SMEM = 3 * TILE_SM + 2 * 128 * (int)sizeof(int) + 64;   // ~105.5 KB
    cudaFuncSetAttribute(hist_kernel, cudaFuncAttributeMaxDynamicSharedMemorySize, SMEM);

    zero_kernel<<<256, 256>>>();
    count_kernel<<<(N_SAMP + 255) / 256, 256>>>(labels);
    prep_kernel<<<(N_SAMP * (EMB / 2) + 255) / 256, 256>>>(X);

    dim3 grid(CG, 64);            // 128 CTAs, one wave
    hist_kernel<<<grid, THREADS, SMEM>>>(labels);

    finalize_kernel<<<(N_SAMP + 255) / 256, 256>>>(labels);
    loss_kernel<<<1, 1>>>(out);
}

// round 9
// speedup vs baseline: 10.6040x; 1.0962x over previous
#include <cuda_runtime.h>
#include <cuda_bf16.h>
#include <cstdint>

#define N_SAMP  8192
#define EMB     128
#define NBINS   10
#define LBINS   11
#define HP      16
#define THREADS 256
#define CG      4                    // col groups (grid.x)
#define CTILE   64                   // cols per CTA tile
#define TPC     (N_SAMP / CG / CTILE)   // 32 col tiles per CTA
#define PB      272                  // smem tile row pitch in bytes (136 bf16)
#define A_SM    (128 * PB)           // 34816 B  (128 x 128 bf16)
#define B_SM    (CTILE * PB)         // 17408 B  (64 x 128 bf16)

// ---------------- device scratch ----------------
__device__ __nv_bfloat16 g_Xb[N_SAMP * EMB];   // bf16 X, row-major (K-major)
__device__ float g_all[N_SAMP * HP];           // all-pairs soft hist
__device__ float g_pos[N_SAMP * HP];           // positive-pair soft hist
__device__ int   g_cls[8192];
__device__ float g_ap_sum;
__device__ float g_nvalid;

// ---------------- PTX helpers ----------------
static __device__ __forceinline__ uint32_t s2u(const void* p) {
    uint32_t a;
    asm("{ .reg .u64 t; cvta.to.shared.u64 t, %1; cvt.u32.u64 %0, t; }" : "=r"(a) : "l"(p));
    return a;
}
#define CP_ASYNC16(dst, src) \
    asm volatile("cp.async.cg.shared.global [%0], [%1], 16;" :: "r"(dst), "l"(src) : "memory")
#define CP_COMMIT() asm volatile("cp.async.commit_group;" ::: "memory")
#define CP_WAIT0()  asm volatile("cp.async.wait_group 0;" ::: "memory")

#define LDSM4(R, addr) \
    asm volatile("ldmatrix.sync.aligned.m8n8.x4.shared.b16 {%0,%1,%2,%3}, [%4];" \
        : "=r"((R)[0]), "=r"((R)[1]), "=r"((R)[2]), "=r"((R)[3]) : "r"(addr))

#define MMA16816(C, A, b0v, b1v) \
    asm volatile("mma.sync.aligned.m16n8k16.row.col.f32.bf16.bf16.f32 " \
        "{%0,%1,%2,%3},{%4,%5,%6,%7},{%8,%9},{%0,%1,%2,%3};" \
        : "+f"((C)[0]), "+f"((C)[1]), "+f"((C)[2]), "+f"((C)[3]) \
        : "r"((A)[0]), "r"((A)[1]), "r"((A)[2]), "r"((A)[3]), "r"(b0v), "r"(b1v))

// ---------------- small kernels ----------------
__global__ void zero_kernel() {
    int i = blockIdx.x * blockDim.x + threadIdx.x;
    int stride = gridDim.x * blockDim.x;
    for (int idx = i; idx < N_SAMP * HP; idx += stride) { g_all[idx] = 0.0f; g_pos[idx] = 0.0f; }
    for (int idx = i; idx < 8192; idx += stride) g_cls[idx] = 0;
    if (i == 0) { g_ap_sum = 0.0f; g_nvalid = 0.0f; }
}

__global__ void count_kernel(const int* __restrict__ labels) {
    int i = blockIdx.x * blockDim.x + threadIdx.x;
    if (i < N_SAMP) {
        int l = labels[i];
        if (l >= 0 && l < 8192) atomicAdd(&g_cls[l], 1);
    }
}

__global__ void prep_kernel(const float* __restrict__ X) {
    int i = blockIdx.x * blockDim.x + threadIdx.x;     // N_SAMP * 64
    if (i < N_SAMP * (EMB / 2)) {
        float2 v = ((const float2*)X)[i];
        ((__nv_bfloat162*)g_Xb)[i] = __float22bfloat162_rn(v);
    }
}

// ---------------- fused HMMA GEMM + soft-hist ----------------
// grid (CG, 64): blockIdx.y = 128-row block, blockIdx.x = group of TPC 64-col tiles.
// 8 warps, 4(m) x 2(n) warp grid, warp tile 32x32, CTA tile 128x64.
extern __shared__ char smem_raw[];

__global__ __launch_bounds__(THREADS, 2)
void hist_kernel(const int* __restrict__ labels) {
    const int tid  = threadIdx.x;
    const int lane = tid & 31;
    const int warp = tid >> 5;
    const int wm   = warp >> 1;          // 0..3: row quarter (32 rows)
    const int wn   = warp & 1;           // 0..1: col half (32 cols)
    const int rb   = blockIdx.y;
    const int cg   = blockIdx.x;

    const uint32_t uS = s2u(smem_raw);
    const uint32_t uA = uS;
    const uint32_t uBb[2] = { uS + A_SM, uS + A_SM + B_SM };
    int* sLab = (int*)(smem_raw + A_SM + 2 * B_SM);     // [2][CTILE]

    // ---- load A tile (128x128) + B tile 0 (64x128) via cp.async ----
    {
        const char* gA = (const char*)(g_Xb + (size_t)rb * 128 * EMB);
        for (int i = tid; i < 2048; i += THREADS) {
            int row = i >> 4, c = i & 15;
            CP_ASYNC16(uA + row * PB + c * 16, gA + row * 256 + c * 16);
        }
        int sc = cg * (TPC * CTILE);
        const char* gB = (const char*)(g_Xb + (size_t)sc * EMB);
        for (int i = tid; i < 1024; i += THREADS) {
            int row = i >> 4, c = i & 15;
            CP_ASYNC16(uBb[0] + row * PB + c * 16, gB + row * 256 + c * 16);
        }
        if (tid < CTILE) sLab[tid] = labels[sc + tid];
    }
    CP_COMMIT();
    CP_WAIT0();
    __syncthreads();

    const int g  = lane >> 2;
    const int tq = lane & 3;

    int lrow[4], myLab[4];
    lrow[0] = wm * 32 + g;  lrow[1] = lrow[0] + 8;
    lrow[2] = lrow[0] + 16; lrow[3] = lrow[0] + 24;
    #pragma unroll
    for (int r = 0; r < 4; r++) myLab[r] = labels[rb * 128 + lrow[r]];

    int lcol[8];
    #pragma unroll
    for (int j = 0; j < 4; j++) {
        lcol[j * 2]     = wn * 32 + j * 8 + tq * 2;
        lcol[j * 2 + 1] = lcol[j * 2] + 1;
    }

    float h[4][5];                       // register hist: bins 3..7
    #pragma unroll
    for (int r = 0; r < 4; r++)
        #pragma unroll
        for (int b = 0; b < 5; b++) h[r][b] = 0.0f;

    const uint32_t aBase = uA + (uint32_t)((wm * 32 + (lane & 15)) * PB + (lane >> 4) * 16);
    const uint32_t bRowOff = (uint32_t)((wn * 32 + (lane & 7) + ((lane >> 4) & 1) * 8) * PB
                                        + ((lane >> 3) & 1) * 16);

    for (int t = 0; t < TPC; t++) {
        const int buf = t & 1;

        // prefetch B[t+1]
        if (t + 1 < TPC) {
            int sc = cg * (TPC * CTILE) + (t + 1) * CTILE;
            const char* gB = (const char*)(g_Xb + (size_t)sc * EMB);
            uint32_t dB = uBb[buf ^ 1];
            for (int i = tid; i < 1024; i += THREADS) {
                int row = i >> 4, c = i & 15;
                CP_ASYNC16(dB + row * PB + c * 16, gB + row * 256 + c * 16);
            }
            CP_COMMIT();
            if (tid < CTILE) sLab[(buf ^ 1) * CTILE + tid] = labels[sc + tid];
        }

        // ---- GEMM: 128x64 tile, warp computes 32x32 ----
        float acc[2][4][4];
        #pragma unroll
        for (int mi = 0; mi < 2; mi++)
            #pragma unroll
            for (int j = 0; j < 4; j++)
                #pragma unroll
                for (int e = 0; e < 4; e++) acc[mi][j][e] = 0.0f;

        const uint32_t uBt = uBb[buf] + bRowOff;
        #pragma unroll
        for (int kc = 0; kc < 8; kc++) {
            uint32_t A0[4], A1[4], B0[4], B1[4];
            LDSM4(A0, aBase + kc * 32);
            LDSM4(A1, aBase + 16 * PB + kc * 32);
            LDSM4(B0, uBt + kc * 32);             // n-tiles 0,1
            LDSM4(B1, uBt + 16 * PB + kc * 32);   // n-tiles 2,3
            MMA16816(acc[0][0], A0, B0[0], B0[1]);
            MMA16816(acc[0][1], A0, B0[2], B0[3]);
            MMA16816(acc[0][2], A0, B1[0], B1[1]);
            MMA16816(acc[0][3], A0, B1[2], B1[3]);
            MMA16816(acc[1][0], A1, B0[0], B0[1]);
            MMA16816(acc[1][1], A1, B0[2], B0[3]);
            MMA16816(acc[1][2], A1, B1[0], B1[1]);
            MMA16816(acc[1][3], A1, B1[2], B1[3]);
        }

        // ---- epilogue: soft-bin 32 dot products ----
        const int colBase   = cg * (TPC * CTILE) + t * CTILE;
        const bool diagTile = ((colBase >> 7) == rb);
        int clab[8];
        #pragma unroll
        for (int li = 0; li < 8; li++) clab[li] = sLab[buf * CTILE + lcol[li]];

        #pragma unroll
        for (int mi = 0; mi < 2; mi++) {
            #pragma unroll
            for (int j = 0; j < 4; j++) {
                #pragma unroll
                for (int e = 0; e < 4; e++) {
                    const int ri = mi * 2 + (e >> 1);
                    const int li = j * 2 + (e & 1);
                    float tv = fmaf(acc[mi][j][e], -5.0f, 5.0f);   // 2.5 * dist2
                    bool isdiag = diagTile && (colBase + lcol[li] == rb * 128 + lrow[ri]);
                    if (!isdiag) {
                        #pragma unroll
                        for (int b = 0; b < 5; b++)
                            h[ri][b] += fmaxf(1.0f - fabsf(tv - (float)(b + 3)), 0.0f);
                        if (clab[li] == myLab[ri]) {               // positive pair (~1%)
                            int grow = rb * 128 + lrow[ri];
                            float tp = fmaxf(tv, 0.0f);
                            int l0 = min((int)tp, 9);
                            float fr = tp - (float)l0;
                            atomicAdd(&g_pos[grow * HP + l0],     1.0f - fr);
                            atomicAdd(&g_pos[grow * HP + l0 + 1], fr);
                        }
                        if (tv < 3.0f) {                           // bins 0..2 (~3e-6)
                            int grow = rb * 128 + lrow[ri];
                            #pragma unroll
                            for (int b = 0; b <= 2; b++) {
                                float w = 1.0f - fabsf(tv - (float)b);
                                if (w > 0.0f) atomicAdd(&g_all[grow * HP + b], w);
                            }
                        }
                        if (tv > 7.0f) {                           // bins 8..10 (~3e-6)
                            int grow = rb * 128 + lrow[ri];
                            #pragma unroll
                            for (int b = 8; b <= 10; b++) {
                                float w = 1.0f - fabsf(tv - (float)b);
                                if (w > 0.0f) atomicAdd(&g_all[grow * HP + b], w);
                            }
                        }
                    }
                }
            }
        }

        CP_WAIT0();
        __syncthreads();
    }

    // flush register hists (bins 3..7)
    #pragma unroll
    for (int ri = 0; ri < 4; ri++) {
        int grow = rb * 128 + lrow[ri];
        #pragma unroll
        for (int b = 0; b < 5; b++)
            atomicAdd(&g_all[grow * HP + 3 + b], h[ri][b]);
    }
}

// ---------------- finalize ----------------
__global__ void finalize_kernel(const int* __restrict__ labels) {
    int i = blockIdx.x * blockDim.x + threadIdx.x;
    float val = 0.0f, valid = 0.0f;
    if (i < N_SAMP) {
        float4 a0 = *(const float4*)&g_all[i * HP + 0];
        float4 a1 = *(const float4*)&g_all[i * HP + 4];
        float4 a2 = *(const float4*)&g_all[i * HP + 8];
        float  aA[12] = {a0.x,a0.y,a0.z,a0.w,a1.x,a1.y,a1.z,a1.w,a2.x,a2.y,a2.z,0.0f};
        float4 p0 = *(const float4*)&g_pos[i * HP + 0];
        float4 p1 = *(const float4*)&g_pos[i * HP + 4];
        float4 p2 = *(const float4*)&g_pos[i * HP + 8];
        float  pA[12] = {p0.x,p0.y,p0.z,p0.w,p1.x,p1.y,p1.z,p1.w,p2.x,p2.y,p2.z,0.0f};
        float Hp = 0.0f, H = 0.0f, ap = 0.0f;
        #pragma unroll
        for (int l = 0; l < LBINS; l++) {
            Hp += pA[l];
            H  += aA[l];
            if (H > 0.0f) ap += pA[l] * Hp / H;
        }
        int np = g_cls[labels[i]] - 1;
        if (np > 0) { val = ap / (float)np; valid = 1.0f; }
    }
    #pragma unroll
    for (int off = 16; off > 0; off >>= 1) {
        val   += __shfl_down_sync(0xffffffffu, val, off);
        valid += __shfl_down_sync(0xffffffffu, valid, off);
    }
    if ((threadIdx.x & 31) == 0) {
        atomicAdd(&g_ap_sum, val);
        atomicAdd(&g_nvalid, valid);
    }
}

__global__ void loss_kernel(float* out) {
    out[0] = 1.0f - g_ap_sum / g_nvalid;
}

// ---------------- launch ----------------
extern "C" void kernel_launch(void* const* d_in, const int* in_sizes, int n_in,
                              void* d_out, int out_size) {
    const float* X      = (const float*)d_in[0];
    const int*   labels = (const int*)d_in[1];
    float*       out    = (float*)d_out;

    const int SMEM = A_SM + 2 * B_SM + 2 * CTILE * (int)sizeof(int) + 64;  // ~70.3 KB
    cudaFuncSetAttribute(hist_kernel, cudaFuncAttributeMaxDynamicSharedMemorySize, SMEM);

    zero_kernel<<<256, 256>>>();
    count_kernel<<<(N_SAMP + 255) / 256, 256>>>(labels);
    prep_kernel<<<(N_SAMP * (EMB / 2) + 255) / 256, 256>>>(X);

    dim3 grid(CG, 64);            // 256 CTAs, 2 per SM, single wave
    hist_kernel<<<grid, THREADS, SMEM>>>(labels);

    finalize_kernel<<<(N_SAMP + 255) / 256, 256>>>(labels);
    loss_kernel<<<1, 1>>>(out);
}

// round 10
// speedup vs baseline: 13.4773x; 1.2710x over previous
#include <cuda_runtime.h>
#include <cuda_bf16.h>
#include <cstdint>

#define N_SAMP  8192
#define EMB     128
#define NBINS   10
#define LBINS   11
#define HP      16
#define THREADS 512
#define CG      4                    // col groups (grid.x)
#define CTILE   64                   // cols per CTA tile
#define TPC     (N_SAMP / CG / CTILE)   // 32 col tiles per CTA
#define PB      272                  // smem tile row pitch in bytes (136 bf16)
#define A_SM    (128 * PB)           // 34816 B  (128 x 128 bf16)
#define B_SM    (CTILE * PB)         // 17408 B  (64 x 128 bf16)

// ---------------- device scratch ----------------
__device__ __nv_bfloat16 g_Xb[N_SAMP * EMB];   // bf16 X, row-major (K-major)
__device__ float g_all[N_SAMP * HP];           // all-pairs soft hist
__device__ float g_pos[N_SAMP * HP];           // positive-pair soft hist
__device__ int   g_cls[8192];
__device__ float g_ap_sum;
__device__ float g_nvalid;

// ---------------- PTX helpers ----------------
static __device__ __forceinline__ uint32_t s2u(const void* p) {
    uint32_t a;
    asm("{ .reg .u64 t; cvta.to.shared.u64 t, %1; cvt.u32.u64 %0, t; }" : "=r"(a) : "l"(p));
    return a;
}
#define CP_ASYNC16(dst, src) \
    asm volatile("cp.async.cg.shared.global [%0], [%1], 16;" :: "r"(dst), "l"(src) : "memory")
#define CP_COMMIT() asm volatile("cp.async.commit_group;" ::: "memory")
#define CP_WAIT0()  asm volatile("cp.async.wait_group 0;" ::: "memory")

#define LDSM4(R, addr) \
    asm volatile("ldmatrix.sync.aligned.m8n8.x4.shared.b16 {%0,%1,%2,%3}, [%4];" \
        : "=r"((R)[0]), "=r"((R)[1]), "=r"((R)[2]), "=r"((R)[3]) : "r"(addr))

#define MMA16816(C, A, b0v, b1v) \
    asm volatile("mma.sync.aligned.m16n8k16.row.col.f32.bf16.bf16.f32 " \
        "{%0,%1,%2,%3},{%4,%5,%6,%7},{%8,%9},{%0,%1,%2,%3};" \
        : "+f"((C)[0]), "+f"((C)[1]), "+f"((C)[2]), "+f"((C)[3]) \
        : "r"((A)[0]), "r"((A)[1]), "r"((A)[2]), "r"((A)[3]), "r"(b0v), "r"(b1v))

// ---------------- small kernels ----------------
__global__ void zero_kernel() {
    int i = blockIdx.x * blockDim.x + threadIdx.x;
    int stride = gridDim.x * blockDim.x;
    for (int idx = i; idx < N_SAMP * HP; idx += stride) { g_all[idx] = 0.0f; g_pos[idx] = 0.0f; }
    for (int idx = i; idx < 8192; idx += stride) g_cls[idx] = 0;
    if (i == 0) { g_ap_sum = 0.0f; g_nvalid = 0.0f; }
}

__global__ void count_kernel(const int* __restrict__ labels) {
    int i = blockIdx.x * blockDim.x + threadIdx.x;
    if (i < N_SAMP) {
        int l = labels[i];
        if (l >= 0 && l < 8192) atomicAdd(&g_cls[l], 1);
    }
}

__global__ void prep_kernel(const float* __restrict__ X) {
    int i = blockIdx.x * blockDim.x + threadIdx.x;     // N_SAMP * 64
    if (i < N_SAMP * (EMB / 2)) {
        float2 v = ((const float2*)X)[i];
        ((__nv_bfloat162*)g_Xb)[i] = __float22bfloat162_rn(v);
    }
}

// ---------------- fused HMMA GEMM + soft-hist ----------------
// grid (CG, 64): blockIdx.y = 128-row block, blockIdx.x = group of TPC 64-col tiles.
// 16 warps, 8(m) x 2(n) warp grid, warp tile 16x32, CTA tile 128x64.
extern __shared__ char smem_raw[];

template<bool DIAG>
static __device__ __forceinline__ void epilogue_tile(
    const float acc[4][4], float h[2][5],
    const int* clab, const int* myLab, const int* lcol, const int* lrow,
    int colBase, int rowGlobalBase)
{
    #pragma unroll
    for (int j = 0; j < 4; j++) {
        #pragma unroll
        for (int e = 0; e < 4; e++) {
            const int ri = e >> 1;
            const int li = j * 2 + (e & 1);
            float tv = fmaf(acc[j][e], -5.0f, 5.0f);   // 2.5 * dist2
            if (DIAG) {
                if (colBase + lcol[li] == rowGlobalBase + lrow[ri]) continue;
            }
            #pragma unroll
            for (int b = 0; b < 5; b++)
                h[ri][b] += fmaxf(1.0f - fabsf(tv - (float)(b + 3)), 0.0f);
            if (clab[li] == myLab[ri]) {               // positive pair (~1%)
                int grow = rowGlobalBase + lrow[ri];
                float tp = fmaxf(tv, 0.0f);
                int l0 = min((int)tp, 9);
                float fr = tp - (float)l0;
                atomicAdd(&g_pos[grow * HP + l0],     1.0f - fr);
                atomicAdd(&g_pos[grow * HP + l0 + 1], fr);
            }
            if (fabsf(tv - 5.0f) >= 2.0f) {            // out-of-window (~3e-6)
                int grow = rowGlobalBase + lrow[ri];
                #pragma unroll
                for (int b = 0; b <= 2; b++) {
                    float w = 1.0f - fabsf(tv - (float)b);
                    if (w > 0.0f) atomicAdd(&g_all[grow * HP + b], w);
                }
                #pragma unroll
                for (int b = 8; b <= 10; b++) {
                    float w = 1.0f - fabsf(tv - (float)b);
                    if (w > 0.0f) atomicAdd(&g_all[grow * HP + b], w);
                }
            }
        }
    }
}

__global__ __launch_bounds__(THREADS, 2)
void hist_kernel(const int* __restrict__ labels) {
    const int tid  = threadIdx.x;
    const int lane = tid & 31;
    const int warp = tid >> 5;
    const int wm   = warp >> 1;          // 0..7: 16-row slice
    const int wn   = warp & 1;           // 0..1: 32-col half
    const int rb   = blockIdx.y;
    const int cg   = blockIdx.x;

    const uint32_t uS = s2u(smem_raw);
    const uint32_t uA = uS;
    const uint32_t uBb[2] = { uS + A_SM, uS + A_SM + B_SM };
    int* sLab = (int*)(smem_raw + A_SM + 2 * B_SM);     // [2][CTILE]

    // ---- load A tile (128x128) + B tile 0 (64x128) via cp.async ----
    {
        const char* gA = (const char*)(g_Xb + (size_t)rb * 128 * EMB);
        for (int i = tid; i < 2048; i += THREADS) {
            int row = i >> 4, c = i & 15;
            CP_ASYNC16(uA + row * PB + c * 16, gA + row * 256 + c * 16);
        }
        int sc = cg * (TPC * CTILE);
        const char* gB = (const char*)(g_Xb + (size_t)sc * EMB);
        for (int i = tid; i < 1024; i += THREADS) {
            int row = i >> 4, c = i & 15;
            CP_ASYNC16(uBb[0] + row * PB + c * 16, gB + row * 256 + c * 16);
        }
        if (tid < CTILE) sLab[tid] = labels[sc + tid];
    }
    CP_COMMIT();
    CP_WAIT0();
    __syncthreads();

    const int g  = lane >> 2;
    const int tq = lane & 3;

    int lrow[2], myLab[2];
    lrow[0] = wm * 16 + g;  lrow[1] = lrow[0] + 8;
    myLab[0] = labels[rb * 128 + lrow[0]];
    myLab[1] = labels[rb * 128 + lrow[1]];

    int lcol[8];
    #pragma unroll
    for (int j = 0; j < 4; j++) {
        lcol[j * 2]     = wn * 32 + j * 8 + tq * 2;
        lcol[j * 2 + 1] = lcol[j * 2] + 1;
    }

    float h[2][5];                       // register hist: bins 3..7
    #pragma unroll
    for (int r = 0; r < 2; r++)
        #pragma unroll
        for (int b = 0; b < 5; b++) h[r][b] = 0.0f;

    const uint32_t aBase = uA + (uint32_t)((wm * 16 + (lane & 15)) * PB + (lane >> 4) * 16);
    const uint32_t bRowOff = (uint32_t)((wn * 32 + (lane & 7) + ((lane >> 4) & 1) * 8) * PB
                                        + ((lane >> 3) & 1) * 16);

    for (int t = 0; t < TPC; t++) {
        const int buf = t & 1;

        // prefetch B[t+1]
        if (t + 1 < TPC) {
            int sc = cg * (TPC * CTILE) + (t + 1) * CTILE;
            const char* gB = (const char*)(g_Xb + (size_t)sc * EMB);
            uint32_t dB = uBb[buf ^ 1];
            for (int i = tid; i < 1024; i += THREADS) {
                int row = i >> 4, c = i & 15;
                CP_ASYNC16(dB + row * PB + c * 16, gB + row * 256 + c * 16);
            }
            CP_COMMIT();
            if (tid < CTILE) sLab[(buf ^ 1) * CTILE + tid] = labels[sc + tid];
        }

        // ---- GEMM: 128x64 tile, warp computes 16x32 ----
        float acc[4][4];
        #pragma unroll
        for (int j = 0; j < 4; j++)
            #pragma unroll
            for (int e = 0; e < 4; e++) acc[j][e] = 0.0f;

        const uint32_t uBt = uBb[buf] + bRowOff;
        #pragma unroll
        for (int kc = 0; kc < 8; kc++) {
            uint32_t A0[4], B0[4], B1[4];
            LDSM4(A0, aBase + kc * 32);
            LDSM4(B0, uBt + kc * 32);             // n-tiles 0,1
            LDSM4(B1, uBt + 16 * PB + kc * 32);   // n-tiles 2,3
            MMA16816(acc[0], A0, B0[0], B0[1]);
            MMA16816(acc[1], A0, B0[2], B0[3]);
            MMA16816(acc[2], A0, B1[0], B1[1]);
            MMA16816(acc[3], A0, B1[2], B1[3]);
        }

        // ---- epilogue: soft-bin 16 dot products ----
        const int colBase = cg * (TPC * CTILE) + t * CTILE;
        int clab[8];
        #pragma unroll
        for (int li = 0; li < 8; li++) clab[li] = sLab[buf * CTILE + lcol[li]];

        if ((colBase >> 7) == rb)
            epilogue_tile<true >(acc, h, clab, myLab, lcol, lrow, colBase, rb * 128);
        else
            epilogue_tile<false>(acc, h, clab, myLab, lcol, lrow, colBase, rb * 128);

        CP_WAIT0();
        __syncthreads();
    }

    // flush register hists (bins 3..7)
    #pragma unroll
    for (int ri = 0; ri < 2; ri++) {
        int grow = rb * 128 + lrow[ri];
        #pragma unroll
        for (int b = 0; b < 5; b++)
            atomicAdd(&g_all[grow * HP + 3 + b], h[ri][b]);
    }
}

// ---------------- finalize ----------------
__global__ void finalize_kernel(const int* __restrict__ labels) {
    int i = blockIdx.x * blockDim.x + threadIdx.x;
    float val = 0.0f, valid = 0.0f;
    if (i < N_SAMP) {
        float4 a0 = *(const float4*)&g_all[i * HP + 0];
        float4 a1 = *(const float4*)&g_all[i * HP + 4];
        float4 a2 = *(const float4*)&g_all[i * HP + 8];
        float  aA[12] = {a0.x,a0.y,a0.z,a0.w,a1.x,a1.y,a1.z,a1.w,a2.x,a2.y,a2.z,0.0f};
        float4 p0 = *(const float4*)&g_pos[i * HP + 0];
        float4 p1 = *(const float4*)&g_pos[i * HP + 4];
        float4 p2 = *(const float4*)&g_pos[i * HP + 8];
        float  pA[12] = {p0.x,p0.y,p0.z,p0.w,p1.x,p1.y,p1.z,p1.w,p2.x,p2.y,p2.z,0.0f};
        float Hp = 0.0f, H = 0.0f, ap = 0.0f;
        #pragma unroll
        for (int l = 0; l < LBINS; l++) {
            Hp += pA[l];
            H  += aA[l];
            if (H > 0.0f) ap += pA[l] * Hp / H;
        }
        int np = g_cls[labels[i]] - 1;
        if (np > 0) { val = ap / (float)np; valid = 1.0f; }
    }
    #pragma unroll
    for (int off = 16; off > 0; off >>= 1) {
        val   += __shfl_down_sync(0xffffffffu, val, off);
        valid += __shfl_down_sync(0xffffffffu, valid, off);
    }
    if ((threadIdx.x & 31) == 0) {
        atomicAdd(&g_ap_sum, val);
        atomicAdd(&g_nvalid, valid);
    }
}

__global__ void loss_kernel(float* out) {
    out[0] = 1.0f - g_ap_sum / g_nvalid;
}

// ---------------- launch ----------------
extern "C" void kernel_launch(void* const* d_in, const int* in_sizes, int n_in,
                              void* d_out, int out_size) {
    const float* X      = (const float*)d_in[0];
    const int*   labels = (const int*)d_in[1];
    float*       out    = (float*)d_out;

    const int SMEM = A_SM + 2 * B_SM + 2 * CTILE * (int)sizeof(int) + 64;  // ~70.3 KB
    cudaFuncSetAttribute(hist_kernel, cudaFuncAttributeMaxDynamicSharedMemorySize, SMEM);

    zero_kernel<<<256, 256>>>();
    count_kernel<<<(N_SAMP + 255) / 256, 256>>>(labels);
    prep_kernel<<<(N_SAMP * (EMB / 2) + 255) / 256, 256>>>(X);

    dim3 grid(CG, 64);            // 256 CTAs, 2 per SM, single wave
    hist_kernel<<<grid, THREADS, SMEM>>>(labels);

    finalize_kernel<<<(N_SAMP + 255) / 256, 256>>>(labels);
    loss_kernel<<<1, 1>>>(out);
}